// round 3
// baseline (speedup 1.0000x reference)
#include <cuda_runtime.h>
#include <cuda_bf16.h>
#include <mma.h>

using namespace nvcuda;

typedef __nv_bfloat16  bf16;
typedef __nv_bfloat162 bf162;

#define B_  64
#define T_  512
#define E_  256
#define U_  256
#define G_  1024
#define O_  20
#define KC  104          // LSTM wh K-rows cached in smem (104*2KB = 208KB)

// ---------------- static device scratch (no allocation allowed) ----------------
__device__ __align__(16) bf16  g_e[B_*T_*E_];            // 16.8MB  bf16 embedded tokens
__device__ __align__(16) float g_zx[67108864];           // 268MB   [dir][b][t][unit*4+gate], bias folded
__device__ __align__(16) bf16  g_wxp[2][E_*G_];          // packed wx
__device__ __align__(16) bf16  g_whp[2][U_*G_];          // packed wh
__device__ __align__(16) float g_bp[2][G_];              // packed bias
__device__ __align__(16) bf16  g_convw[3*E_*256];
__device__ __align__(16) bf16  g_c[B_*T_*256];           // conv output (post relu)
__device__ __align__(16) bf16  g_p[B_*128*256];          // pooled = flattened f
__device__ __align__(16) bf16  g_d1wT[8388608];          // d1_w transposed [256][32768]
__device__ __align__(16) float g_d1[B_*256];
__device__ __align__(16) float g_h[2][B_*U_];

// ---------------- embedding gather f32 -> bf16 ----------------
__global__ void k_gather(const int* __restrict__ tokens, const float* __restrict__ emb) {
    int i = blockIdx.x * blockDim.x + threadIdx.x;   // 1,048,576 threads, 8 elems each
    int bt = i >> 5, seg = i & 31;
    int tok = tokens[bt];
    const float4* s = (const float4*)(emb + (size_t)tok * E_ + seg * 8);
    float4 a = s[0], b = s[1];
    bf162 o0 = __floats2bfloat162_rn(a.x, a.y);
    bf162 o1 = __floats2bfloat162_rn(a.z, a.w);
    bf162 o2 = __floats2bfloat162_rn(b.x, b.y);
    bf162 o3 = __floats2bfloat162_rn(b.z, b.w);
    uint4 pk;
    pk.x = *(unsigned*)&o0; pk.y = *(unsigned*)&o1;
    pk.z = *(unsigned*)&o2; pk.w = *(unsigned*)&o3;
    *((uint4*)(g_e + (size_t)bt * E_ + seg * 8)) = pk;
}

// ---------------- weight prep ----------------
// pack gate order: dst[r][j*4+g] = src[r][g*256+j]   (g: 0=i,1=f,2=g,3=o)
__global__ void k_pack_g(const float* __restrict__ src, int dir, int which) {
    int i = blockIdx.x * blockDim.x + threadIdx.x;   // 262144
    int r = i >> 10, p = i & 1023, j = p >> 2, g = p & 3;
    bf16 v = __float2bfloat16(src[r * G_ + g * 256 + j]);
    if (which == 0) g_wxp[dir][i] = v; else g_whp[dir][i] = v;
}
__global__ void k_pack_b(const float* __restrict__ src, int dir) {
    int p = blockIdx.x * blockDim.x + threadIdx.x;   // 1024
    g_bp[dir][p] = src[(p & 3) * 256 + (p >> 2)];
}
__global__ void k_cvt_convw(const float* __restrict__ s) {
    int i = blockIdx.x * blockDim.x + threadIdx.x;   // 196608
    g_convw[i] = __float2bfloat16(s[i]);
}
__global__ void k_d1wT(const float* __restrict__ s) {
    size_t i = (size_t)blockIdx.x * blockDim.x + threadIdx.x;  // 8,388,608
    int c = (int)(i >> 15), k = (int)(i & 32767);
    g_d1wT[i] = __float2bfloat16(s[(size_t)k * 256 + c]);
}

// ---------------- tiled WMMA GEMM: 64x64 tile, 4 warps x (32x32) ----------------
// MODE 0: zx = e @ wxp + bp  -> f32 g_zx       (M=32768, N=1024, K=256)
// MODE 1: conv im2col GEMM, relu(x+conv_b) -> bf16 g_c  (M=32768, N=256, K=768)
template<int MODE>
__global__ void __launch_bounds__(128) k_gemm(int dir, const float* __restrict__ bias_in, int Kdim) {
    __shared__ __align__(16) bf16  As[64][40];
    __shared__ __align__(16) bf16  Bs[32][72];
    __shared__ __align__(16) float Cs[64][68];

    const int tid = threadIdx.x;
    const int m0 = blockIdx.y * 64, n0 = blockIdx.x * 64;
    const int Ncols = (MODE == 0) ? 1024 : 256;
    const bf16* Bm = (MODE == 0) ? g_wxp[dir] : g_convw;
    const float* bias = (MODE == 0) ? g_bp[dir] : bias_in;

    wmma::fragment<wmma::accumulator, 16, 16, 16, float> acc[2][2];
    for (int i = 0; i < 2; i++)
        for (int j = 0; j < 2; j++) wmma::fill_fragment(acc[i][j], 0.f);

    const int wid = tid >> 5, wm = wid >> 1, wn = wid & 1;

    for (int k0 = 0; k0 < Kdim; k0 += 32) {
        // A tile: 64 rows x 32 k  (256 uint4, 2 per thread)
        #pragma unroll
        for (int l = 0; l < 2; l++) {
            int v = tid + l * 128;
            int row = v >> 2, vc = v & 3;
            uint4 val;
            if (MODE == 0) {
                val = *(const uint4*)(g_e + (size_t)(m0 + row) * E_ + k0 + vc * 8);
            } else {
                int m = m0 + row, b = m >> 9, t = m & 511;
                int w = k0 >> 8, eo = (k0 & 255) + vc * 8;
                int st = t + w - 1;
                if (st >= 0 && st < 512)
                    val = *(const uint4*)(g_e + ((size_t)(b << 9) + st) * E_ + eo);
                else
                    val = make_uint4(0u, 0u, 0u, 0u);
            }
            *(uint4*)&As[row][vc * 8] = val;
        }
        // B tile: 32 k-rows x 64 cols
        #pragma unroll
        for (int l = 0; l < 2; l++) {
            int v = tid + l * 128;
            int row = v >> 3, vc = v & 7;
            *(uint4*)&Bs[row][vc * 8] = *(const uint4*)(Bm + (size_t)(k0 + row) * Ncols + n0 + vc * 8);
        }
        __syncthreads();
        #pragma unroll
        for (int ks = 0; ks < 32; ks += 16) {
            wmma::fragment<wmma::matrix_a, 16, 16, 16, bf16, wmma::row_major> af[2];
            wmma::fragment<wmma::matrix_b, 16, 16, 16, bf16, wmma::row_major> bfr[2];
            #pragma unroll
            for (int i = 0; i < 2; i++) wmma::load_matrix_sync(af[i], &As[wm * 32 + i * 16][ks], 40);
            #pragma unroll
            for (int j = 0; j < 2; j++) wmma::load_matrix_sync(bfr[j], &Bs[ks][wn * 32 + j * 16], 72);
            #pragma unroll
            for (int i = 0; i < 2; i++)
                #pragma unroll
                for (int j = 0; j < 2; j++)
                    wmma::mma_sync(acc[i][j], af[i], bfr[j], acc[i][j]);
        }
        __syncthreads();
    }
    #pragma unroll
    for (int i = 0; i < 2; i++)
        #pragma unroll
        for (int j = 0; j < 2; j++)
            wmma::store_matrix_sync(&Cs[wm * 32 + i * 16][wn * 32 + j * 16], acc[i][j], 68, wmma::mem_row_major);
    __syncthreads();
    #pragma unroll
    for (int l = 0; l < 8; l++) {
        int v = tid + l * 128;
        int row = v >> 4, vc = v & 15;
        float4 c = *(float4*)&Cs[row][vc * 4];
        float4 bb = *(const float4*)(bias + n0 + vc * 4);
        c.x += bb.x; c.y += bb.y; c.z += bb.z; c.w += bb.w;
        if (MODE == 0) {
            *(float4*)(g_zx + (size_t)dir * 33554432ull + (size_t)(m0 + row) * 1024 + n0 + vc * 4) = c;
        } else {
            c.x = fmaxf(c.x, 0.f); c.y = fmaxf(c.y, 0.f);
            c.z = fmaxf(c.z, 0.f); c.w = fmaxf(c.w, 0.f);
            bf162 p0 = __floats2bfloat162_rn(c.x, c.y);
            bf162 p1 = __floats2bfloat162_rn(c.z, c.w);
            uint2 pk; pk.x = *(unsigned*)&p0; pk.y = *(unsigned*)&p1;
            *(uint2*)(g_c + (size_t)(m0 + row) * 256 + n0 + vc * 4) = pk;
        }
    }
}

// ---------------- maxpool (size=stride=4 along T) ----------------
__global__ void k_pool() {
    int i = blockIdx.x * blockDim.x + threadIdx.x;   // 2,097,152 = 64*128*256
    int oc = i & 255, rest = i >> 8;
    int b = rest >> 7, tp = rest & 127;
    size_t base = ((size_t)b * 512 + tp * 4) * 256 + oc;
    float m = __bfloat162float(g_c[base]);
    m = fmaxf(m, __bfloat162float(g_c[base + 256]));
    m = fmaxf(m, __bfloat162float(g_c[base + 512]));
    m = fmaxf(m, __bfloat162float(g_c[base + 768]));
    g_p[i] = __float2bfloat16(m);
}

// ---------------- d1 = f @ d1_w + b   (warp-dot, K=32768) ----------------
__device__ __forceinline__ float dot8(uint4 a, uint4 b) {
    float s = 0.f;
    const bf162* pa = (const bf162*)&a;
    const bf162* pb = (const bf162*)&b;
    #pragma unroll
    for (int q = 0; q < 4; q++) {
        float2 fa = __bfloat1622float2(pa[q]);
        float2 fb = __bfloat1622float2(pb[q]);
        s += fa.x * fb.x + fa.y * fb.y;
    }
    return s;
}
__global__ void __launch_bounds__(256) k_d1(const float* __restrict__ d1_b) {
    int b = blockIdx.x >> 2, cc = blockIdx.x & 3;
    int warp = threadIdx.x >> 5, lane = threadIdx.x & 31;
    const uint4* f4 = (const uint4*)g_p + (size_t)b * 4096;   // 32768 bf16 = 4096 uint4
    for (int ci = 0; ci < 8; ci++) {
        int col = cc * 64 + warp * 8 + ci;
        const uint4* w4 = (const uint4*)g_d1wT + (size_t)col * 4096;
        float s = 0.f;
        for (int i = lane; i < 4096; i += 32) s += dot8(f4[i], w4[i]);
        #pragma unroll
        for (int o = 16; o; o >>= 1) s += __shfl_xor_sync(0xffffffffu, s, o);
        if (lane == 0) g_d1[b * 256 + col] = s + d1_b[col];
    }
}

// ---------------- LSTM recurrence: 128 independent blocks (dir x batch) ----------------
__global__ void __launch_bounds__(256) k_lstm() {
    extern __shared__ char sm[];
    bf16*  whs  = (bf16*)sm;                       // KC*1024 bf16
    float* h_sh = (float*)(sm + KC * 2048);        // 256 f32

    const int tid = threadIdx.x;
    const int dir = blockIdx.x >> 6, b = blockIdx.x & 63;
    const bf16* whg = g_whp[dir];

    // cache first KC K-rows of packed wh in smem
    {
        const uint4* src = (const uint4*)whg;
        uint4* dst = (uint4*)whs;
        for (int i = tid; i < KC * 128; i += 256) dst[i] = src[i];
    }
    h_sh[tid] = 0.f;
    float c = 0.f;
    const float* zxb = g_zx + (size_t)dir * 33554432ull + (size_t)b * T_ * 1024;
    const float2* ws2 = (const float2*)whs;
    const float2* wg2 = (const float2*)whg;
    __syncthreads();

    for (int t = 0; t < T_; t++) {
        int tt = dir ? (T_ - 1 - t) : t;
        float a0 = 0.f, a1 = 0.f, a2 = 0.f, a3 = 0.f;
        #pragma unroll 8
        for (int k = 0; k < KC; k++) {
            float hk = h_sh[k];
            float2 w = ws2[k * 256 + tid];
            bf162 lo = *(bf162*)&w.x, hi = *(bf162*)&w.y;
            float2 f0 = __bfloat1622float2(lo), f1 = __bfloat1622float2(hi);
            a0 += hk * f0.x; a1 += hk * f0.y; a2 += hk * f1.x; a3 += hk * f1.y;
        }
        #pragma unroll 8
        for (int k = KC; k < 256; k++) {
            float hk = h_sh[k];
            float2 w = wg2[k * 256 + tid];
            bf162 lo = *(bf162*)&w.x, hi = *(bf162*)&w.y;
            float2 f0 = __bfloat1622float2(lo), f1 = __bfloat1622float2(hi);
            a0 += hk * f0.x; a1 += hk * f0.y; a2 += hk * f1.x; a3 += hk * f1.y;
        }
        float4 z = *(const float4*)(zxb + (size_t)tt * 1024 + tid * 4);
        float zi = z.x + a0, zf = z.y + a1, zg = z.z + a2, zo = z.w + a3;
        float ig = 1.f / (1.f + __expf(-zi));
        float fg = 1.f / (1.f + __expf(-zf));
        float gg = tanhf(zg);
        float og = 1.f / (1.f + __expf(-zo));
        c = fg * c + ig * gg;
        float h = og * tanhf(c);
        __syncthreads();
        h_sh[tid] = h;
        __syncthreads();
    }
    g_h[dir][b * 256 + tid] = h_sh[tid];
}

// ---------------- d2 + concat + output + softmax ----------------
__global__ void __launch_bounds__(256) k_final(const float* __restrict__ d2_w, const float* __restrict__ d2_b,
                                               const float* __restrict__ out_w, const float* __restrict__ out_b,
                                               float* __restrict__ out) {
    __shared__ float r[512];
    __shared__ float con[512];
    __shared__ float lg[O_];
    int b = blockIdx.x, tid = threadIdx.x;
    r[tid]       = g_h[0][b * 256 + tid];
    r[256 + tid] = g_h[1][b * 256 + tid];
    con[tid]     = g_d1[b * 256 + tid];
    __syncthreads();
    float s = d2_b[tid];
    for (int k = 0; k < 512; k++) s += r[k] * d2_w[k * 256 + tid];
    con[256 + tid] = s;
    __syncthreads();
    if (tid < O_) {
        float l = out_b[tid];
        for (int k = 0; k < 512; k++) l += con[k] * out_w[k * O_ + tid];
        lg[tid] = l;
    }
    __syncthreads();
    if (tid == 0) {
        float mx = lg[0];
        for (int j = 1; j < O_; j++) mx = fmaxf(mx, lg[j]);
        float e[O_], ss = 0.f;
        for (int j = 0; j < O_; j++) { e[j] = __expf(lg[j] - mx); ss += e[j]; }
        float inv = 1.f / ss;
        for (int j = 0; j < O_; j++) out[b * O_ + j] = e[j] * inv;
    }
}

// ---------------- launcher ----------------
extern "C" void kernel_launch(void* const* d_in, const int* in_sizes, int n_in,
                              void* d_out, int out_size) {
    const int*   tokens = (const int*)  d_in[0];
    const float* emb    = (const float*)d_in[1];
    const float* conv_w = (const float*)d_in[2];
    const float* conv_b = (const float*)d_in[3];
    const float* d1_w   = (const float*)d_in[4];
    const float* d1_b   = (const float*)d_in[5];
    const float* wx_f   = (const float*)d_in[6];
    const float* wh_f   = (const float*)d_in[7];
    const float* b_f    = (const float*)d_in[8];
    const float* wx_b   = (const float*)d_in[9];
    const float* wh_b   = (const float*)d_in[10];
    const float* b_b    = (const float*)d_in[11];
    const float* d2_w   = (const float*)d_in[12];
    const float* d2_b   = (const float*)d_in[13];
    const float* out_w  = (const float*)d_in[14];
    const float* out_b  = (const float*)d_in[15];
    float* out = (float*)d_out;

    cudaFuncSetAttribute(k_lstm, cudaFuncAttributeMaxDynamicSharedMemorySize, KC * 2048 + 1024);

    k_gather<<<4096, 256>>>(tokens, emb);
    k_pack_g<<<1024, 256>>>(wx_f, 0, 0);
    k_pack_g<<<1024, 256>>>(wx_b, 1, 0);
    k_pack_g<<<1024, 256>>>(wh_f, 0, 1);
    k_pack_g<<<1024, 256>>>(wh_b, 1, 1);
    k_pack_b<<<4, 256>>>(b_f, 0);
    k_pack_b<<<4, 256>>>(b_b, 1);
    k_cvt_convw<<<768, 256>>>(conv_w);
    k_d1wT<<<32768, 256>>>(d1_w);

    k_gemm<0><<<dim3(16, 512), 128>>>(0, nullptr, 256);   // zx forward
    k_gemm<0><<<dim3(16, 512), 128>>>(1, nullptr, 256);   // zx backward
    k_gemm<1><<<dim3(4, 512), 128>>>(0, conv_b, 768);     // conv1d (im2col)

    k_pool<<<8192, 256>>>();
    k_d1<<<256, 256>>>(d1_b);

    k_lstm<<<128, 256, KC * 2048 + 1024>>>();

    k_final<<<64, 256>>>(d2_w, d2_b, out_w, out_b, out);
}

// round 6
// speedup vs baseline: 3.0386x; 3.0386x over previous
#include <cuda_runtime.h>
#include <cuda_bf16.h>
#include <mma.h>

using namespace nvcuda;

typedef __nv_bfloat16  bf16;
typedef __nv_bfloat162 bf162;

#define B_  64
#define T_  512
#define E_  256
#define U_  256
#define G_  1024
#define O_  20
#define KC  108          // LSTM wh K-rows pinned in smem (108*2KB = 216KB)

// ---------------- static device scratch ----------------
__device__ __align__(16) bf16  g_e[B_*T_*E_];            // 16.8MB
__device__ __align__(16) float g_zx[67108864];           // 268MB [dir][b][t][j*4+gate]
__device__ __align__(16) bf16  g_wxp[2][E_*G_];
__device__ __align__(16) bf16  g_whp[2][U_*G_];
__device__ __align__(16) float g_bp[2][G_];
__device__ __align__(16) bf16  g_convw[3*E_*256];
__device__ __align__(16) bf16  g_c[B_*T_*256];
__device__ __align__(16) bf16  g_p[B_*128*256];
__device__ __align__(16) float g_d1p[256*B_*256];        // split-K partials 16.8MB
__device__ __align__(16) float g_h[2][B_*U_];

// ---------------- cp.async helpers ----------------
__device__ __forceinline__ void cpa16(void* dst, const void* src, int sz) {
    unsigned d = (unsigned)__cvta_generic_to_shared(dst);
    asm volatile("cp.async.cg.shared.global [%0], [%1], 16, %2;\n" :: "r"(d), "l"(src), "r"(sz));
}
__device__ __forceinline__ void cpa_commit() { asm volatile("cp.async.commit_group;\n"); }
template<int N> __device__ __forceinline__ void cpa_wait() { asm volatile("cp.async.wait_group %0;\n" :: "n"(N)); }

__device__ __forceinline__ float sigf(float x) { return 1.f / (1.f + __expf(-x)); }
__device__ __forceinline__ float tanhap(float x) {
    float r; asm("tanh.approx.f32 %0, %1;" : "=f"(r) : "f"(x)); return r;
}

// ---------------- 1: embedding gather f32 -> bf16 ----------------
__global__ void k_gather(const int* __restrict__ tokens, const float* __restrict__ emb) {
    int i = blockIdx.x * blockDim.x + threadIdx.x;
    int bt = i >> 5, seg = i & 31;
    int tok = tokens[bt];
    const float4* s = (const float4*)(emb + (size_t)tok * E_ + seg * 8);
    float4 a = s[0], b = s[1];
    bf162 o0 = __floats2bfloat162_rn(a.x, a.y);
    bf162 o1 = __floats2bfloat162_rn(a.z, a.w);
    bf162 o2 = __floats2bfloat162_rn(b.x, b.y);
    bf162 o3 = __floats2bfloat162_rn(b.z, b.w);
    uint4 pk;
    pk.x = *(unsigned*)&o0; pk.y = *(unsigned*)&o1;
    pk.z = *(unsigned*)&o2; pk.w = *(unsigned*)&o3;
    *((uint4*)(g_e + (size_t)bt * E_ + seg * 8)) = pk;
}

// ---------------- 2: merged weight prep ----------------
// gate pack: dst[r][j*4+g] = src[r][g*256+j]
__device__ __forceinline__ void packg(bf16* dst, const float* src, int i) {
    int r = i >> 10, p = i & 1023, j = p >> 2, g = p & 3;
    dst[i] = __float2bfloat16(src[r * G_ + g * 256 + j]);
}
__global__ void k_prep(const float* __restrict__ wx_f, const float* __restrict__ wx_b,
                       const float* __restrict__ wh_f, const float* __restrict__ wh_b,
                       const float* __restrict__ b_f,  const float* __restrict__ b_b,
                       const float* __restrict__ conv_w) {
    int i = blockIdx.x * blockDim.x + threadIdx.x;
    if (i < 262144)            packg(g_wxp[0], wx_f, i);
    else if (i < 524288)       packg(g_wxp[1], wx_b, i - 262144);
    else if (i < 786432)       packg(g_whp[0], wh_f, i - 524288);
    else if (i < 1048576)      packg(g_whp[1], wh_b, i - 786432);
    else if (i < 1049600)    { int p = i - 1048576; g_bp[0][p] = b_f[(p & 3) * 256 + (p >> 2)]; }
    else if (i < 1050624)    { int p = i - 1049600; g_bp[1][p] = b_b[(p & 3) * 256 + (p >> 2)]; }
    else if (i < 1247232)    { int p = i - 1050624; g_convw[p] = __float2bfloat16(conv_w[p]); }
}

// ---------------- 3/4: double-buffered 128x128 WMMA GEMM ----------------
// MODE 0: zx = e @ wxp + bp (f32 out, dir=blockIdx.z)   M=32768 N=1024 K=256
// MODE 1: conv im2col GEMM, relu -> bf16 g_c            M=32768 N=256  K=768
template<int MODE>
__global__ void __launch_bounds__(256) k_gemm(const float* __restrict__ bias_in, int Kdim) {
    extern __shared__ char smx[];
    bf16*  As = (bf16*)smx;               // [2][128][40]
    bf16*  Bs = (bf16*)(smx + 20480);     // [2][32][136]
    float* Cs = (float*)smx;              // [128][132] (reuses stage smem)

    const int tid = threadIdx.x;
    const int dir = blockIdx.z;
    const int m0 = blockIdx.y * 128, n0 = blockIdx.x * 128;
    const int Ncols = (MODE == 0) ? 1024 : 256;
    const bf16* Bm = (MODE == 0) ? g_wxp[dir] : g_convw;
    const float* bias = (MODE == 0) ? g_bp[dir] : bias_in;

    const int wid = tid >> 5;
    const int wm = wid & 3, wn = wid >> 2;   // 4x2 warp grid; warp tile 32x64

    wmma::fragment<wmma::accumulator, 16, 16, 16, float> acc[2][4];
    #pragma unroll
    for (int i = 0; i < 2; i++)
        #pragma unroll
        for (int j = 0; j < 4; j++) wmma::fill_fragment(acc[i][j], 0.f);

    auto load_stage = [&](int s, int k0) {
        #pragma unroll
        for (int l = 0; l < 2; l++) {
            int v = tid + l * 256, row = v >> 2, c = (v & 3) * 8;
            bf16* dst = As + s * 5120 + row * 40 + c;
            if (MODE == 0) {
                cpa16(dst, g_e + (size_t)(m0 + row) * 256 + k0 + c, 16);
            } else {
                int m = m0 + row, bb = m >> 9, t = m & 511;
                int w = k0 >> 8, eo = (k0 & 255) + c;
                int st = t + w - 1;
                int stc = st < 0 ? 0 : (st > 511 ? 511 : st);
                cpa16(dst, g_e + ((size_t)(bb << 9) + stc) * 256 + eo,
                      (st >= 0 && st < 512) ? 16 : 0);
            }
        }
        #pragma unroll
        for (int l = 0; l < 2; l++) {
            int v = tid + l * 256, row = v >> 4, c = (v & 15) * 8;
            cpa16(Bs + s * 4352 + row * 136 + c, Bm + (size_t)(k0 + row) * Ncols + n0 + c, 16);
        }
    };

    const int nK = Kdim >> 5;
    load_stage(0, 0); cpa_commit();
    for (int kc = 0; kc < nK; kc++) {
        if (kc + 1 < nK) { load_stage((kc + 1) & 1, (kc + 1) * 32); cpa_commit(); cpa_wait<1>(); }
        else             { cpa_wait<0>(); }
        __syncthreads();
        const bf16* A0 = As + (kc & 1) * 5120;
        const bf16* B0 = Bs + (kc & 1) * 4352;
        #pragma unroll
        for (int ks = 0; ks < 32; ks += 16) {
            wmma::fragment<wmma::matrix_a, 16, 16, 16, bf16, wmma::row_major> af[2];
            wmma::fragment<wmma::matrix_b, 16, 16, 16, bf16, wmma::row_major> bfr[4];
            #pragma unroll
            for (int i = 0; i < 2; i++)
                wmma::load_matrix_sync(af[i], A0 + (wm * 32 + i * 16) * 40 + ks, 40);
            #pragma unroll
            for (int j = 0; j < 4; j++)
                wmma::load_matrix_sync(bfr[j], B0 + ks * 136 + wn * 64 + j * 16, 136);
            #pragma unroll
            for (int i = 0; i < 2; i++)
                #pragma unroll
                for (int j = 0; j < 4; j++)
                    wmma::mma_sync(acc[i][j], af[i], bfr[j], acc[i][j]);
        }
        __syncthreads();
    }

    #pragma unroll
    for (int i = 0; i < 2; i++)
        #pragma unroll
        for (int j = 0; j < 4; j++)
            wmma::store_matrix_sync(Cs + (wm * 32 + i * 16) * 132 + wn * 64 + j * 16,
                                    acc[i][j], 132, wmma::mem_row_major);
    __syncthreads();
    #pragma unroll
    for (int l = 0; l < 16; l++) {
        int v = tid + l * 256, row = v >> 5, c = (v & 31) * 4;
        float4 cv = *(float4*)(Cs + row * 132 + c);
        float4 bb = *(const float4*)(bias + n0 + c);
        cv.x += bb.x; cv.y += bb.y; cv.z += bb.z; cv.w += bb.w;
        if (MODE == 0) {
            *(float4*)(g_zx + (size_t)dir * 33554432ull + (size_t)(m0 + row) * 1024 + n0 + c) = cv;
        } else {
            cv.x = fmaxf(cv.x, 0.f); cv.y = fmaxf(cv.y, 0.f);
            cv.z = fmaxf(cv.z, 0.f); cv.w = fmaxf(cv.w, 0.f);
            bf162 p0 = __floats2bfloat162_rn(cv.x, cv.y);
            bf162 p1 = __floats2bfloat162_rn(cv.z, cv.w);
            uint2 pk; pk.x = *(unsigned*)&p0; pk.y = *(unsigned*)&p1;
            *(uint2*)(g_c + (size_t)(m0 + row) * 256 + n0 + c) = pk;
        }
    }
}

// ---------------- 5: maxpool ----------------
__global__ void k_pool() {
    int i = blockIdx.x * blockDim.x + threadIdx.x;
    int oc = i & 255, rest = i >> 8;
    int b = rest >> 7, tp = rest & 127;
    size_t base = ((size_t)b * 512 + tp * 4) * 256 + oc;
    float m = __bfloat162float(g_c[base]);
    m = fmaxf(m, __bfloat162float(g_c[base + 256]));
    m = fmaxf(m, __bfloat162float(g_c[base + 512]));
    m = fmaxf(m, __bfloat162float(g_c[base + 768]));
    g_p[i] = __float2bfloat16(m);
}

// ---------------- 6: LSTM recurrence (launch #6 -> gets profiled) ----------------
__global__ void __launch_bounds__(256) k_lstm() {
    extern __shared__ char sm[];
    bf16*  whs  = (bf16*)sm;                       // [KC][1024]
    float* hbuf = (float*)(sm + KC * 2048);        // 2 x 256 ping-pong

    const int tid = threadIdx.x;
    const int dir = blockIdx.x >> 6, b = blockIdx.x & 63;
    const bf16* whg = g_whp[dir];

    {   // pin first KC rows
        const uint4* src = (const uint4*)whg;
        uint4* dst = (uint4*)whs;
        for (int i = tid; i < KC * 128; i += 256) dst[i] = src[i];
    }
    hbuf[tid] = 0.f; hbuf[256 + tid] = 0.f;
    float c = 0.f, hout = 0.f;
    const float* zxb = g_zx + (size_t)dir * 33554432ull + (size_t)b * T_ * 1024;
    const float2* ws2 = (const float2*)whs;
    const float2* wg2 = (const float2*)whg;
    __syncthreads();

    int cur = 0;
    float2 bufA[8], bufB[8];
    for (int t = 0; t < T_; t++) {
        const int tt = dir ? (T_ - 1 - t) : t;
        const float* hc = hbuf + cur * 256;
        float4 z = *(const float4*)(zxb + (size_t)tt * 1024 + tid * 4);  // early load
        // prefetch first streamed chunk (hidden under pinned loop)
        #pragma unroll
        for (int j = 0; j < 8; j++) bufA[j] = wg2[(KC + j) * 256 + tid];

        float a0 = 0.f, a1 = 0.f, a2 = 0.f, a3 = 0.f;
        #pragma unroll 8
        for (int k = 0; k < KC; k++) {
            float hk = hc[k];
            float2 w = ws2[k * 256 + tid];
            unsigned u0 = *(unsigned*)&w.x, u1 = *(unsigned*)&w.y;
            a0 += hk * __uint_as_float(u0 << 16);
            a1 += hk * __uint_as_float(u0 & 0xFFFF0000u);
            a2 += hk * __uint_as_float(u1 << 16);
            a3 += hk * __uint_as_float(u1 & 0xFFFF0000u);
        }
        // streamed 148 rows: first 4, then 9 double-buffered groups of 16
        {   // rows KC..KC+3 via bufB staging (keeps indices simple: 148 = 4 + 9*16)
            #pragma unroll
            for (int j = 0; j < 4; j++) {
                float hk = hc[KC + j];   // bufA holds KC..KC+7; use first 4 now
                unsigned u0 = *(unsigned*)&bufA[j].x, u1 = *(unsigned*)&bufA[j].y;
                a0 += hk * __uint_as_float(u0 << 16);
                a1 += hk * __uint_as_float(u0 & 0xFFFF0000u);
                a2 += hk * __uint_as_float(u1 << 16);
                a3 += hk * __uint_as_float(u1 & 0xFFFF0000u);
            }
            #pragma unroll
            for (int j = 0; j < 4; j++) bufA[j] = bufA[j + 4];   // shift remaining 4
        }
        #pragma unroll 1
        for (int g2 = 0; g2 < 9; g2++) {
            int kb = KC + 4 + g2 * 16;   // consume rows kb..kb+15
            // bufA currently holds rows kb..kb+3 (4 regs); load kb+4..kb+11 into bufB
            #pragma unroll
            for (int j = 0; j < 8; j++) bufB[j] = wg2[(kb + 4 + j) * 256 + tid];
            #pragma unroll
            for (int j = 0; j < 4; j++) {
                float hk = hc[kb + j];
                unsigned u0 = *(unsigned*)&bufA[j].x, u1 = *(unsigned*)&bufA[j].y;
                a0 += hk * __uint_as_float(u0 << 16);
                a1 += hk * __uint_as_float(u0 & 0xFFFF0000u);
                a2 += hk * __uint_as_float(u1 << 16);
                a3 += hk * __uint_as_float(u1 & 0xFFFF0000u);
            }
            // load next 8 (kb+12..kb+19; last group clamps into valid range <=255)
            #pragma unroll
            for (int j = 0; j < 8; j++) {
                int kk = kb + 12 + j;
                bufA[j < 4 ? j : j] = (j < 4)
                    ? wg2[(kk) * 256 + tid]
                    : ((kk < 256) ? wg2[kk * 256 + tid] : make_float2(0.f, 0.f));
            }
            #pragma unroll
            for (int j = 0; j < 8; j++) {
                float hk = hc[kb + 4 + j];
                unsigned u0 = *(unsigned*)&bufB[j].x, u1 = *(unsigned*)&bufB[j].y;
                a0 += hk * __uint_as_float(u0 << 16);
                a1 += hk * __uint_as_float(u0 & 0xFFFF0000u);
                a2 += hk * __uint_as_float(u1 << 16);
                a3 += hk * __uint_as_float(u1 & 0xFFFF0000u);
            }
            // consume rows kb+12..kb+15 from bufA[0..3]; bufA[4..7] = next group's head
            #pragma unroll
            for (int j = 0; j < 4; j++) {
                float hk = hc[kb + 12 + j];
                unsigned u0 = *(unsigned*)&bufA[j].x, u1 = *(unsigned*)&bufA[j].y;
                a0 += hk * __uint_as_float(u0 << 16);
                a1 += hk * __uint_as_float(u0 & 0xFFFF0000u);
                a2 += hk * __uint_as_float(u1 << 16);
                a3 += hk * __uint_as_float(u1 & 0xFFFF0000u);
            }
            #pragma unroll
            for (int j = 0; j < 4; j++) bufA[j] = bufA[j + 4];
        }
        float ig = sigf(z.x + a0);
        float fg = sigf(z.y + a1);
        float gg = tanhap(z.z + a2);
        float og = sigf(z.w + a3);
        c = fg * c + ig * gg;
        hout = og * tanhap(c);
        hbuf[(cur ^ 1) * 256 + tid] = hout;
        __syncthreads();
        cur ^= 1;
    }
    g_h[dir][b * 256 + tid] = hout;
}

// ---------------- 7: d1 split-K (each weight element read exactly once) ----------------
__global__ void __launch_bounds__(256) k_d1s(const float* __restrict__ d1_w) {
    extern __shared__ char sm[];
    bf16* ws = (bf16*)sm;                 // [128][256] bf16 = 64KB
    bf16* fs = (bf16*)(sm + 65536);       // [64][128]  bf16 = 16KB
    const int tid = threadIdx.x;
    const int j = blockIdx.x;             // 256 K-slices of 128
    const int k0 = j * 128;

    // weights: 32768 consecutive f32 -> bf16 smem (coalesced)
    const float4* wsrc = (const float4*)(d1_w + (size_t)k0 * 256);
    for (int i = tid; i < 8192; i += 256) {
        float4 v = wsrc[i];
        bf162 p0 = __floats2bfloat162_rn(v.x, v.y);
        bf162 p1 = __floats2bfloat162_rn(v.z, v.w);
        uint2 pk; pk.x = *(unsigned*)&p0; pk.y = *(unsigned*)&p1;
        *(uint2*)(ws + i * 4) = pk;
    }
    // f slice: per b, 128 contiguous bf16
    for (int i = tid; i < 1024; i += 256) {
        int b = i >> 4, kk = i & 15;
        ((uint4*)fs)[i] = *((const uint4*)(g_p + (size_t)b * 32768 + k0) + kk);
    }
    __syncthreads();

    const int cc = tid;
    for (int b = 0; b < 64; b++) {
        float s = 0.f;
        #pragma unroll 8
        for (int k = 0; k < 128; k++)
            s += __bfloat162float(fs[b * 128 + k]) * __bfloat162float(ws[k * 256 + cc]);
        g_d1p[(size_t)j * 16384 + b * 256 + cc] = s;
    }
}

// ---------------- 8: d1 reduce + d2 + output + softmax ----------------
__global__ void __launch_bounds__(256) k_final(const float* __restrict__ d1_b,
                                               const float* __restrict__ d2_w, const float* __restrict__ d2_b,
                                               const float* __restrict__ out_w, const float* __restrict__ out_b,
                                               float* __restrict__ out) {
    __shared__ float r[512];
    __shared__ float con[512];
    __shared__ float lg[O_];
    int b = blockIdx.x, tid = threadIdx.x;
    r[tid]       = g_h[0][b * 256 + tid];
    r[256 + tid] = g_h[1][b * 256 + tid];
    float s1 = d1_b[tid];
    #pragma unroll 8
    for (int j = 0; j < 256; j++) s1 += g_d1p[(size_t)j * 16384 + b * 256 + tid];
    con[tid] = s1;
    __syncthreads();
    float s = d2_b[tid];
    for (int k = 0; k < 512; k++) s += r[k] * d2_w[k * 256 + tid];
    con[256 + tid] = s;
    __syncthreads();
    if (tid < O_) {
        float l = out_b[tid];
        for (int k = 0; k < 512; k++) l += con[k] * out_w[k * O_ + tid];
        lg[tid] = l;
    }
    __syncthreads();
    if (tid == 0) {
        float mx = lg[0];
        for (int j = 1; j < O_; j++) mx = fmaxf(mx, lg[j]);
        float e[O_], ss = 0.f;
        for (int j = 0; j < O_; j++) { e[j] = __expf(lg[j] - mx); ss += e[j]; }
        float inv = 1.f / ss;
        for (int j = 0; j < O_; j++) out[b * O_ + j] = e[j] * inv;
    }
}

// ---------------- launcher ----------------
extern "C" void kernel_launch(void* const* d_in, const int* in_sizes, int n_in,
                              void* d_out, int out_size) {
    const int*   tokens = (const int*)  d_in[0];
    const float* emb    = (const float*)d_in[1];
    const float* conv_w = (const float*)d_in[2];
    const float* conv_b = (const float*)d_in[3];
    const float* d1_w   = (const float*)d_in[4];
    const float* d1_b   = (const float*)d_in[5];
    const float* wx_f   = (const float*)d_in[6];
    const float* wh_f   = (const float*)d_in[7];
    const float* b_f    = (const float*)d_in[8];
    const float* wx_b   = (const float*)d_in[9];
    const float* wh_b   = (const float*)d_in[10];
    const float* b_b    = (const float*)d_in[11];
    const float* d2_w   = (const float*)d_in[12];
    const float* d2_b   = (const float*)d_in[13];
    const float* out_w  = (const float*)d_in[14];
    const float* out_b  = (const float*)d_in[15];
    float* out = (float*)d_out;

    const int GEMM_SMEM = 67584;
    const int LSTM_SMEM = KC * 2048 + 2048;   // 223232
    const int D1_SMEM   = 81920;
    cudaFuncSetAttribute(k_gemm<0>, cudaFuncAttributeMaxDynamicSharedMemorySize, GEMM_SMEM);
    cudaFuncSetAttribute(k_gemm<1>, cudaFuncAttributeMaxDynamicSharedMemorySize, GEMM_SMEM);
    cudaFuncSetAttribute(k_lstm,    cudaFuncAttributeMaxDynamicSharedMemorySize, LSTM_SMEM);
    cudaFuncSetAttribute(k_d1s,     cudaFuncAttributeMaxDynamicSharedMemorySize, D1_SMEM);

    k_gather<<<4096, 256>>>(tokens, emb);                                  // 1
    k_prep<<<4872, 256>>>(wx_f, wx_b, wh_f, wh_b, b_f, b_b, conv_w);       // 2
    k_gemm<0><<<dim3(8, 256, 2), 256, GEMM_SMEM>>>(nullptr, 256);          // 3 zx both dirs
    k_gemm<1><<<dim3(2, 256, 1), 256, GEMM_SMEM>>>(conv_b, 768);           // 4 conv
    k_pool<<<8192, 256>>>();                                               // 5
    k_lstm<<<128, 256, LSTM_SMEM>>>();                                     // 6  <- profiled
    k_d1s<<<256, 256, D1_SMEM>>>(d1_w);                                    // 7
    k_final<<<64, 256>>>(d1_b, d2_w, d2_b, out_w, out_b, out);             // 8
}